// round 14
// baseline (speedup 1.0000x reference)
#include <cuda_runtime.h>
#include <cuda_bf16.h>
#include <cstdint>

// ---------------- problem constants ----------------
#define B_ROWS 4096
#define C_CLS  1000
#define NN     8192
#define DD     256

// main kernel tiling: tile = M128 x D128 x K512; 64*2*16 = 2048 tiles
#define MCTA    128
#define DCTA    128
#define KSPLIT  16
#define KC      32
#define KRANGE  (NN / KSPLIT)       // 512
#define NIT     (KRANGE / KC)       // 16 (even: A' parity stable across tiles)
#define TILES   2048
#define PCTA    296
#define THREADS 256

// smem: A' bf16 [128][40] x2, B bf16 [128][40] x3, red region
#define P_STRIDE_H 40
#define APSZ  (MCTA * P_STRIDE_H * 2)     // 10240
#define BSZ   (DCTA * P_STRIDE_H * 2)     // 10240
#define BOFF  (2 * APSZ)                  // 20480
#define REDOFF (2 * APSZ + 3 * BSZ)       // 51200
#define SMEM_BYTES (REDOFF + 128)         // 51328

// ---------------- device scratch ----------------
__device__ __nv_bfloat16 g_ehatT[(size_t)DD * NN];  // Ê^T [256][8192]
__device__ __nv_bfloat16 g_ehatN[(size_t)NN * DD];  // Ê   [8192][256]
__device__ float g_ce[B_ROWS];                      // per-row logZ
__device__ float g_psem[TILES];
__device__ float g_pabs[TILES];
__device__ float g_pplain[TILES];
__device__ int   g_tile;

// ---------------- helpers ----------------
__device__ __forceinline__ uint32_t smem_u32(const void* p) {
    uint32_t a;
    asm("{ .reg .u64 t; cvta.to.shared.u64 t, %1; cvt.u32.u64 %0, t; }" : "=r"(a) : "l"(p));
    return a;
}
__device__ __forceinline__ void cp16(uint32_t s, const void* g) {
    asm volatile("cp.async.cg.shared.global [%0], [%1], 16;" :: "r"(s), "l"(g));
}
__device__ __forceinline__ void cp_commit() {
    asm volatile("cp.async.commit_group;" ::: "memory");
}
__device__ __forceinline__ void ldm_x4(uint32_t* r, uint32_t addr) {
    asm volatile("ldmatrix.sync.aligned.m8n8.x4.shared.b16 {%0,%1,%2,%3}, [%4];"
                 : "=r"(r[0]), "=r"(r[1]), "=r"(r[2]), "=r"(r[3]) : "r"(addr));
}
__device__ __forceinline__ void mma_16816(float* d, const uint32_t* a,
                                          uint32_t b0, uint32_t b1) {
    asm volatile(
        "mma.sync.aligned.m16n8k16.row.col.f32.bf16.bf16.f32 "
        "{%0,%1,%2,%3}, {%4,%5,%6,%7}, {%8,%9}, {%0,%1,%2,%3};"
        : "+f"(d[0]), "+f"(d[1]), "+f"(d[2]), "+f"(d[3])
        : "r"(a[0]), "r"(a[1]), "r"(a[2]), "r"(a[3]), "r"(b0), "r"(b1));
}
__device__ __forceinline__ uint32_t pack_bf16x2(float lo, float hi) {
    __nv_bfloat162 h = __floats2bfloat162_rn(lo, hi);
    return *reinterpret_cast<uint32_t*>(&h);
}

// ---------------- kernel 1: fused pre (norm + CE-logZ + queue reset) ----------------
__global__ void rdl_pre(const float* __restrict__ emb, const float* __restrict__ pred) {
    const int tid = threadIdx.x, lane = tid & 31, wid = tid >> 5;
    if (blockIdx.x == 0 && tid == 0) g_tile = 0;

    if (blockIdx.x < 256) {
        __shared__ float tile[32 * DD];
        __shared__ float rnorm[32];
        const int r0 = blockIdx.x * 32;

        for (int idx = tid; idx < 32 * DD; idx += 256)
            tile[idx] = emb[(size_t)r0 * DD + idx];
        __syncthreads();

#pragma unroll
        for (int q = 0; q < 4; q++) {
            const int rr = wid * 4 + q;
            float s = 0.f;
#pragma unroll
            for (int kk = lane; kk < DD; kk += 32) { float v = tile[rr * DD + kk]; s += v * v; }
#pragma unroll
            for (int o = 16; o; o >>= 1) s += __shfl_xor_sync(0xffffffffu, s, o);
            if (lane == 0) rnorm[rr] = rsqrtf(s);
        }
        __syncthreads();

        const int j = lane;
#pragma unroll
        for (int d8 = 0; d8 < 32; d8++) {
            const int d = d8 * 8 + wid;
            g_ehatT[(size_t)d * NN + r0 + j] = __float2bfloat16(tile[j * DD + d] * rnorm[j]);
        }
        for (int idx = tid; idx < 32 * DD; idx += 256) {
            const int r = idx >> 8;          // DD = 256
            g_ehatN[(size_t)r0 * DD + idx] = __float2bfloat16(tile[idx] * rnorm[r]);
        }
    } else {
        const int row = (blockIdx.x - 256) * 8 + wid;   // 512 blocks x 8 rows
        const float4* p4 = reinterpret_cast<const float4*>(pred + (size_t)row * C_CLS);
        float m = -3.4e38f;
        for (int i = lane; i < C_CLS / 4; i += 32) {
            const float4 v = p4[i];
            m = fmaxf(m, fmaxf(fmaxf(v.x, v.y), fmaxf(v.z, v.w)));
        }
#pragma unroll
        for (int o = 16; o; o >>= 1) m = fmaxf(m, __shfl_xor_sync(0xffffffffu, m, o));
        float s = 0.f;
        for (int i = lane; i < C_CLS / 4; i += 32) {
            const float4 v = p4[i];
            s += expf(v.x - m) + expf(v.y - m) + expf(v.z - m) + expf(v.w - m);
        }
#pragma unroll
        for (int o = 16; o; o >>= 1) s += __shfl_xor_sync(0xffffffffu, s, o);
        if (lane == 0) g_ce[row] = m + logf(s);   // logZ
    }
}

// ---------------- kernel 2: persistent main, continuous cross-tile pipeline ----------------
__device__ __forceinline__ void issueB_st(int stage, int chunk, int tid, uint32_t sb,
                                          int d0, int kbase) {
    const uint32_t sbb = sb + BOFF + (uint32_t)(stage * BSZ);
    const int kb = kbase + chunk * KC;
#pragma unroll
    for (int i = 0; i < 2; i++) {
        const int idx = tid + (i << 8);
        const int r = idx >> 2, c = idx & 3;
        cp16(sbb + r * (P_STRIDE_H * 2) + c * 16,
             reinterpret_cast<const char*>(g_ehatT) +
                 ((size_t)(d0 + r) * NN + (unsigned)(kb + c * 8)) * 2);
    }
    cp_commit();
}

__global__ __launch_bounds__(THREADS, 2) void rdl_main(const float* __restrict__ adj) {
    extern __shared__ char smem[];
    const int tid = threadIdx.x, wid = tid >> 5, lane = tid & 31;
    const uint32_t sb = smem_u32(smem);

    const int mq = wid & 1;                  // M half (64 rows)
    const int dq = wid >> 1;                 // D quarter (32 cols)
    const int g = lane >> 2, c = lane & 3;

    const int lrow = lane & 15, lcol8 = (lane >> 4) << 3;
    const uint32_t a_base = sb + (uint32_t)(((64 * mq + lrow) * P_STRIDE_H + lcol8) * 2);
    const uint32_t b_base0 = sb + BOFF + (uint32_t)(((32 * dq + lrow) * P_STRIDE_H + lcol8) * 2);

    const int cv_r = tid >> 3, cv_c = tid & 7;
    const uint32_t ap_off = (uint32_t)((cv_r * P_STRIDE_H + cv_c * 4) * 2);

    int* tile_sh = reinterpret_cast<int*>(smem + REDOFF + 96);
    float* red = reinterpret_cast<float*>(smem + REDOFF);

    // first claim
    if (tid == 0) *tile_sh = atomicAdd(&g_tile, 1);
    __syncthreads();
    int t = *tile_sh;
    if (t >= TILES) return;

    int row0 = (t & 63) * MCTA;
    int db = (t >> 6) & 1;
    int d0base = db * DCTA;
    int kbase = (t >> 7) * KRANGE;
    const float4* ap = reinterpret_cast<const float4*>(
        adj + (size_t)(row0 + cv_r) * NN + (unsigned)kbase) + cv_c;

    int tn = 0, row0_n = 0, db_n = 0, d0_n = 0, kb_n = 0;
    const float4* ap_n = nullptr;
    bool have_next = true;

    float acc[4][4][4];
#pragma unroll
    for (int mi = 0; mi < 4; mi++)
#pragma unroll
        for (int ni = 0; ni < 4; ni++)
#pragma unroll
            for (int q = 0; q < 4; q++) acc[mi][ni][q] = 0.f;
    float abs_acc = 0.f, plain_acc = 0.f, abs_cr = 0.f, plain_cr = 0.f;
    float4 rv[4];

    // prologue (global iters 0,1 of first tile)
    issueB_st(0, 0, tid, sb, d0base, kbase);
    issueB_st(1, 1, tid, sb, d0base, kbase);
#pragma unroll
    for (int i = 0; i < 4; i++) rv[i] = ap[(size_t)i * 8 * NN];
#pragma unroll
    for (int i = 0; i < 4; i++) {
        const float4 v = rv[i];
        if (db == 0) {
            abs_acc   += fabsf(v.x) + fabsf(v.y) + fabsf(v.z) + fabsf(v.w);
            plain_acc += (v.x + v.y) + (v.z + v.w);
        }
        uint2 u; u.x = pack_bf16x2(v.x, v.y); u.y = pack_bf16x2(v.z, v.w);
        *reinterpret_cast<uint2*>(smem + ap_off + (uint32_t)(i * 32 * P_STRIDE_H * 2)) = u;
    }
#pragma unroll
    for (int i = 0; i < 4; i++) rv[i] = ap[(size_t)i * 8 * NN + 8];

    int st = 0;   // B stage of current iteration (global iter mod 3)

    for (;;) {   // tiles
        for (int it = 0; it < NIT; ++it) {
            if (!have_next && it == NIT - 1)
                asm volatile("cp.async.wait_group 0;" ::: "memory");
            else
                asm volatile("cp.async.wait_group 1;" ::: "memory");
            __syncthreads();

            if (it == NIT - 4 && tid == 0) *tile_sh = atomicAdd(&g_tile, 1);
            if (it == NIT - 3) {
                tn = *tile_sh;
                have_next = (tn < TILES);
                if (have_next) {
                    row0_n = (tn & 63) * MCTA;
                    db_n = (tn >> 6) & 1;
                    d0_n = db_n * DCTA;
                    kb_n = (tn >> 7) * KRANGE;
                    ap_n = reinterpret_cast<const float4*>(
                        adj + (size_t)(row0_n + cv_r) * NN + (unsigned)kb_n) + cv_c;
                }
            }

            // issue B(g+2)
            int st2 = st + 2; if (st2 >= 3) st2 -= 3;
            if (it + 2 < NIT)            issueB_st(st2, it + 2, tid, sb, d0base, kbase);
            else if (have_next)          issueB_st(st2, it + 2 - NIT, tid, sb, d0_n, kb_n);

            // convert A(g+1) from rv
            if (it + 1 < NIT) {
                char* Ap = smem + ((it + 1) & 1) * APSZ;
#pragma unroll
                for (int i = 0; i < 4; i++) {
                    const float4 v = rv[i];
                    if (db == 0) {
                        abs_acc   += fabsf(v.x) + fabsf(v.y) + fabsf(v.z) + fabsf(v.w);
                        plain_acc += (v.x + v.y) + (v.z + v.w);
                    }
                    uint2 u; u.x = pack_bf16x2(v.x, v.y); u.y = pack_bf16x2(v.z, v.w);
                    *reinterpret_cast<uint2*>(Ap + ap_off + (uint32_t)(i * 32 * P_STRIDE_H * 2)) = u;
                }
            } else if (have_next) {      // next tile chunk 0 -> carry accumulators
                char* Ap = smem + 0 * APSZ;   // (g0+NIT)&1 == 0 since NIT even
#pragma unroll
                for (int i = 0; i < 4; i++) {
                    const float4 v = rv[i];
                    if (db_n == 0) {
                        abs_cr   += fabsf(v.x) + fabsf(v.y) + fabsf(v.z) + fabsf(v.w);
                        plain_cr += (v.x + v.y) + (v.z + v.w);
                    }
                    uint2 u; u.x = pack_bf16x2(v.x, v.y); u.y = pack_bf16x2(v.z, v.w);
                    *reinterpret_cast<uint2*>(Ap + ap_off + (uint32_t)(i * 32 * P_STRIDE_H * 2)) = u;
                }
            }

            // prefetch A(g+2) into rv
            if (it + 2 < NIT) {
                const size_t ko = (size_t)(it + 2) * 8;
#pragma unroll
                for (int i = 0; i < 4; i++) rv[i] = ap[(size_t)i * 8 * NN + ko];
            } else if (have_next) {
                const size_t ko = (size_t)(it + 2 - NIT) * 8;
#pragma unroll
                for (int i = 0; i < 4; i++) rv[i] = ap_n[(size_t)i * 8 * NN + ko];
            }

            // mma on A'[it&1], B[st]
            const uint32_t ab = a_base + (uint32_t)((it & 1) * APSZ);
            const uint32_t bb = b_base0 + (uint32_t)(st * BSZ);
#pragma unroll
            for (int kf = 0; kf < 2; kf++) {
                uint32_t bfr[2][4];
#pragma unroll
                for (int pr = 0; pr < 2; pr++)
                    ldm_x4(bfr[pr], bb + (uint32_t)(((pr * 16) * P_STRIDE_H + kf * 16) * 2));
                uint32_t afr[4][4];
#pragma unroll
                for (int mi = 0; mi < 4; mi++)
                    ldm_x4(afr[mi], ab + (uint32_t)(((mi * 16) * P_STRIDE_H + kf * 16) * 2));
#pragma unroll
                for (int mi = 0; mi < 4; mi++)
#pragma unroll
                    for (int ni = 0; ni < 4; ni++)
                        mma_16816(acc[mi][ni], afr[mi],
                                  bfr[ni >> 1][ni & 1], bfr[ni >> 1][(ni & 1) + 2]);
            }
            st = (st == 2) ? 0 : st + 1;
        }

        // epilogue for tile t
        float sem_acc = 0.f;
#pragma unroll
        for (int mi = 0; mi < 4; mi++)
#pragma unroll
            for (int ni = 0; ni < 4; ni++) {
                const int m0 = row0 + 64 * mq + 16 * mi + g;
                const int d0 = d0base + 32 * dq + 8 * ni + 2 * c;
                const __nv_bfloat162 e0 = *reinterpret_cast<const __nv_bfloat162*>(
                    &g_ehatN[(size_t)m0 * DD + d0]);
                const __nv_bfloat162 e1 = *reinterpret_cast<const __nv_bfloat162*>(
                    &g_ehatN[(size_t)(m0 + 8) * DD + d0]);
                sem_acc += acc[mi][ni][0] * __bfloat162float(e0.x)
                         + acc[mi][ni][1] * __bfloat162float(e0.y)
                         + acc[mi][ni][2] * __bfloat162float(e1.x)
                         + acc[mi][ni][3] * __bfloat162float(e1.y);
                acc[mi][ni][0] = 0.f; acc[mi][ni][1] = 0.f;
                acc[mi][ni][2] = 0.f; acc[mi][ni][3] = 0.f;
            }
#pragma unroll
        for (int o = 16; o; o >>= 1) {
            sem_acc   += __shfl_xor_sync(0xffffffffu, sem_acc, o);
            abs_acc   += __shfl_xor_sync(0xffffffffu, abs_acc, o);
            plain_acc += __shfl_xor_sync(0xffffffffu, plain_acc, o);
        }
        __syncthreads();
        if (lane == 0) { red[wid] = sem_acc; red[8 + wid] = abs_acc; red[16 + wid] = plain_acc; }
        __syncthreads();
        if (tid == 0) {
            float s2 = 0.f, a2 = 0.f, p2 = 0.f;
#pragma unroll
            for (int w = 0; w < 8; w++) { s2 += red[w]; a2 += red[8 + w]; p2 += red[16 + w]; }
            g_psem[t] = s2; g_pabs[t] = a2; g_pplain[t] = p2;
        }

        abs_acc = abs_cr;  abs_cr = 0.f;
        plain_acc = plain_cr; plain_cr = 0.f;
        if (!have_next) break;
        t = tn; row0 = row0_n; db = db_n; d0base = d0_n; kbase = kb_n; ap = ap_n;
    }
}

// ---------------- kernel 3: combine (probe + CE gather + final) ----------------
__global__ void rdl_combine(const float* __restrict__ pred, const void* __restrict__ tgt,
                            float* __restrict__ out) {
    const int tid = threadIdx.x, lane = tid & 31, wid = tid >> 5;
    __shared__ float red[4][8];
    __shared__ int any;
    if (tid == 0) any = 0;
    __syncthreads();

    int local = 0;
    for (int i = tid; i < 2048; i += 256) local |= ((const int*)tgt)[2 * i + 1];
    if (local) atomicOr(&any, 1);
    __syncthreads();
    const int is64 = (any == 0);

    float ce = 0.f, sem = 0.f, ab = 0.f, pl = 0.f;
    for (int r = tid; r < B_ROWS; r += 256) {
        int t;
        if (is64) t = (int)((const long long*)tgt)[r];
        else      t = ((const int*)tgt)[r];
        t = min(max(t, 0), C_CLS - 1);
        ce += g_ce[r] - pred[(size_t)r * C_CLS + t];
    }
    for (int i = tid; i < TILES; i += 256) { sem += g_psem[i]; ab += g_pabs[i]; pl += g_pplain[i]; }
#pragma unroll
    for (int o = 16; o; o >>= 1) {
        ce  += __shfl_xor_sync(0xffffffffu, ce, o);
        sem += __shfl_xor_sync(0xffffffffu, sem, o);
        ab  += __shfl_xor_sync(0xffffffffu, ab, o);
        pl  += __shfl_xor_sync(0xffffffffu, pl, o);
    }
    if (lane == 0) { red[0][wid] = ce; red[1][wid] = sem; red[2][wid] = ab; red[3][wid] = pl; }
    __syncthreads();
    if (tid == 0) {
        float tce = 0.f, tsem = 0.f, tab = 0.f, tpl = 0.f;
#pragma unroll
        for (int w = 0; w < 8; w++) {
            tce += red[0][w]; tsem += red[1][w]; tab += red[2][w]; tpl += red[3][w];
        }
        const float invB  = 1.0f / (float)B_ROWS;
        const float invN2 = 1.0f / ((float)NN * (float)NN);
        const float l_task   = tce * invB;
        const float l_sparse = tab * invN2;
        const float l_sem    = (tpl - tsem) * invN2;
        out[0] = 1.0f * l_task + 0.01f * l_sparse + 0.1f * l_sem;
    }
}

// ---------------- launch ----------------
extern "C" void kernel_launch(void* const* d_in, const int* in_sizes, int n_in,
                              void* d_out, int out_size) {
    const float* pred = nullptr; const void* tgt = nullptr;
    const float* adj  = nullptr; const float* emb = nullptr;
    for (int i = 0; i < n_in; i++) {
        switch (in_sizes[i]) {
            case B_ROWS * C_CLS:     pred = (const float*)d_in[i]; break;
            case B_ROWS:             tgt  = d_in[i];               break;
            case NN * NN:            adj  = (const float*)d_in[i]; break;
            case NN * DD:            emb  = (const float*)d_in[i]; break;
            default: break;
        }
    }
    float* out = (float*)d_out;
    (void)out_size;

    rdl_pre<<<768, THREADS>>>(emb, pred);
    cudaFuncSetAttribute(rdl_main, cudaFuncAttributeMaxDynamicSharedMemorySize, SMEM_BYTES);
    rdl_main<<<PCTA, THREADS, SMEM_BYTES>>>(adj);
    rdl_combine<<<1, 256>>>(pred, tgt, out);
}

// round 15
// speedup vs baseline: 1.1332x; 1.1332x over previous
#include <cuda_runtime.h>
#include <cuda_bf16.h>
#include <cstdint>

// ---------------- problem constants ----------------
#define B_ROWS 4096
#define C_CLS  1000
#define NN     8192
#define DD     256

// main kernel tiling: tile = M128 x D128 x K2048; 64*2*4 = 512 tiles
#define MCTA    128
#define DCTA    128
#define KSPLIT  4
#define KC      32
#define KRANGE  (NN / KSPLIT)       // 2048
#define NIT     (KRANGE / KC)       // 64
#define TILES   512
#define PCTA    296                 // 2 CTAs x 148 SMs, persistent
#define THREADS 256

// smem: A' bf16 [128][40] x2, B bf16 [128][40] x3, red region
#define P_STRIDE_H 40
#define APSZ  (MCTA * P_STRIDE_H * 2)     // 10240
#define BSZ   (DCTA * P_STRIDE_H * 2)     // 10240
#define BOFF  (2 * APSZ)                  // 20480
#define REDOFF (2 * APSZ + 3 * BSZ)       // 51200
#define SMEM_BYTES (REDOFF + 128)         // 51328

// ---------------- device scratch ----------------
__device__ __nv_bfloat16 g_ehatT[(size_t)DD * NN];  // Ê^T [256][8192]
__device__ __nv_bfloat16 g_ehatN[(size_t)NN * DD];  // Ê   [8192][256]
__device__ float g_ce[B_ROWS];                      // per-row logZ
__device__ float g_psem[TILES];
__device__ float g_pabs[TILES];
__device__ float g_pplain[TILES];
__device__ int   g_tile;

// ---------------- helpers ----------------
__device__ __forceinline__ uint32_t smem_u32(const void* p) {
    uint32_t a;
    asm("{ .reg .u64 t; cvta.to.shared.u64 t, %1; cvt.u32.u64 %0, t; }" : "=r"(a) : "l"(p));
    return a;
}
__device__ __forceinline__ void cp16(uint32_t s, const void* g) {
    asm volatile("cp.async.cg.shared.global [%0], [%1], 16;" :: "r"(s), "l"(g));
}
__device__ __forceinline__ void cp_commit() {
    asm volatile("cp.async.commit_group;" ::: "memory");
}
__device__ __forceinline__ void ldm_x4(uint32_t* r, uint32_t addr) {
    asm volatile("ldmatrix.sync.aligned.m8n8.x4.shared.b16 {%0,%1,%2,%3}, [%4];"
                 : "=r"(r[0]), "=r"(r[1]), "=r"(r[2]), "=r"(r[3]) : "r"(addr));
}
__device__ __forceinline__ void mma_16816(float* d, const uint32_t* a,
                                          uint32_t b0, uint32_t b1) {
    asm volatile(
        "mma.sync.aligned.m16n8k16.row.col.f32.bf16.bf16.f32 "
        "{%0,%1,%2,%3}, {%4,%5,%6,%7}, {%8,%9}, {%0,%1,%2,%3};"
        : "+f"(d[0]), "+f"(d[1]), "+f"(d[2]), "+f"(d[3])
        : "r"(a[0]), "r"(a[1]), "r"(a[2]), "r"(a[3]), "r"(b0), "r"(b1));
}
__device__ __forceinline__ uint32_t pack_bf16x2(float lo, float hi) {
    __nv_bfloat162 h = __floats2bfloat162_rn(lo, hi);
    return *reinterpret_cast<uint32_t*>(&h);
}

// ---------------- kernel 1: norm-only pre (+ queue reset) ----------------
__global__ void rdl_pre(const float* __restrict__ emb) {
    const int tid = threadIdx.x, lane = tid & 31, wid = tid >> 5;
    if (blockIdx.x == 0 && tid == 0) g_tile = 0;

    __shared__ float tile[32 * DD];
    __shared__ float rnorm[32];
    const int r0 = blockIdx.x * 32;

    for (int idx = tid; idx < 32 * DD; idx += 256)
        tile[idx] = emb[(size_t)r0 * DD + idx];
    __syncthreads();

#pragma unroll
    for (int q = 0; q < 4; q++) {
        const int rr = wid * 4 + q;
        float s = 0.f;
#pragma unroll
        for (int kk = lane; kk < DD; kk += 32) { float v = tile[rr * DD + kk]; s += v * v; }
#pragma unroll
        for (int o = 16; o; o >>= 1) s += __shfl_xor_sync(0xffffffffu, s, o);
        if (lane == 0) rnorm[rr] = rsqrtf(s);
    }
    __syncthreads();

    const int j = lane;
#pragma unroll
    for (int d8 = 0; d8 < 32; d8++) {
        const int d = d8 * 8 + wid;
        g_ehatT[(size_t)d * NN + r0 + j] = __float2bfloat16(tile[j * DD + d] * rnorm[j]);
    }
    for (int idx = tid; idx < 32 * DD; idx += 256) {
        const int r = idx >> 8;          // DD = 256
        g_ehatN[(size_t)r0 * DD + idx] = __float2bfloat16(tile[idx] * rnorm[r]);
    }
}

// ---------------- kernel 2: persistent main (CE pre-phase + GEMM tiles) ----------------
__device__ __forceinline__ void issueB(int it, int tid, uint32_t sb, int d0, int kbase) {
    const uint32_t sbb = sb + BOFF + (uint32_t)((it % 3) * BSZ);
    const int kb = kbase + it * KC;
#pragma unroll
    for (int i = 0; i < 2; i++) {
        const int idx = tid + (i << 8);
        const int r = idx >> 2, c = idx & 3;
        cp16(sbb + r * (P_STRIDE_H * 2) + c * 16,
             reinterpret_cast<const char*>(g_ehatT) +
                 ((size_t)(d0 + r) * NN + (unsigned)(kb + c * 8)) * 2);
    }
    cp_commit();
}

__global__ __launch_bounds__(THREADS, 2) void rdl_main(const float* __restrict__ adj,
                                                       const float* __restrict__ pred) {
    extern __shared__ char smem[];
    const int tid = threadIdx.x, wid = tid >> 5, lane = tid & 31;
    const uint32_t sb = smem_u32(smem);

    // ---- CE pre-phase: per-row logZ, warp-per-row ----
    for (int row = blockIdx.x * 8 + wid; row < B_ROWS; row += PCTA * 8) {
        const float4* p4 = reinterpret_cast<const float4*>(pred + (size_t)row * C_CLS);
        float m = -3.4e38f;
        for (int i = lane; i < C_CLS / 4; i += 32) {
            const float4 v = p4[i];
            m = fmaxf(m, fmaxf(fmaxf(v.x, v.y), fmaxf(v.z, v.w)));
        }
#pragma unroll
        for (int o = 16; o; o >>= 1) m = fmaxf(m, __shfl_xor_sync(0xffffffffu, m, o));
        float s = 0.f;
        for (int i = lane; i < C_CLS / 4; i += 32) {
            const float4 v = p4[i];
            s += expf(v.x - m) + expf(v.y - m) + expf(v.z - m) + expf(v.w - m);
        }
#pragma unroll
        for (int o = 16; o; o >>= 1) s += __shfl_xor_sync(0xffffffffu, s, o);
        if (lane == 0) g_ce[row] = m + logf(s);   // logZ
    }

    // ---- GEMM tile phase (R12 structure) ----
    const int mq = wid & 1;                  // M half (64 rows)
    const int dq = wid >> 1;                 // D quarter (32 cols)
    const int g = lane >> 2, c = lane & 3;

    const int lrow = lane & 15, lcol8 = (lane >> 4) << 3;
    const uint32_t a_base = sb + (uint32_t)(((64 * mq + lrow) * P_STRIDE_H + lcol8) * 2);
    const uint32_t b_base0 = sb + BOFF + (uint32_t)(((32 * dq + lrow) * P_STRIDE_H + lcol8) * 2);

    const int cv_r = tid >> 3, cv_c = tid & 7;
    const uint32_t ap_off = (uint32_t)((cv_r * P_STRIDE_H + cv_c * 4) * 2);

    int* tile_sh = reinterpret_cast<int*>(smem + REDOFF + 96);
    float* red = reinterpret_cast<float*>(smem + REDOFF);

    for (;;) {
        if (tid == 0) *tile_sh = atomicAdd(&g_tile, 1);
        __syncthreads();
        const int t = *tile_sh;
        __syncthreads();
        if (t >= TILES) break;

        const int row0   = (t & 63) * MCTA;
        const int db     = (t >> 6) & 1;
        const int d0base = db * DCTA;
        const int kbase  = (t >> 7) * KRANGE;

        const float4* ap = reinterpret_cast<const float4*>(
            adj + (size_t)(row0 + cv_r) * NN + (unsigned)kbase) + cv_c;

        float acc[4][4][4];
#pragma unroll
        for (int mi = 0; mi < 4; mi++)
#pragma unroll
            for (int ni = 0; ni < 4; ni++)
#pragma unroll
                for (int q = 0; q < 4; q++) acc[mi][ni][q] = 0.f;

        float abs_acc = 0.f, plain_acc = 0.f;
        float4 rv[4];

        // prologue
        issueB(0, tid, sb, d0base, kbase);
        issueB(1, tid, sb, d0base, kbase);
#pragma unroll
        for (int i = 0; i < 4; i++) rv[i] = ap[(size_t)i * 8 * NN];
#pragma unroll
        for (int i = 0; i < 4; i++) {
            const float4 v = rv[i];
            if (db == 0) {
                abs_acc   += fabsf(v.x) + fabsf(v.y) + fabsf(v.z) + fabsf(v.w);
                plain_acc += (v.x + v.y) + (v.z + v.w);
            }
            uint2 u; u.x = pack_bf16x2(v.x, v.y); u.y = pack_bf16x2(v.z, v.w);
            *reinterpret_cast<uint2*>(smem + ap_off + (uint32_t)(i * 32 * P_STRIDE_H * 2)) = u;
        }
#pragma unroll
        for (int i = 0; i < 4; i++) rv[i] = ap[(size_t)i * 8 * NN + 8];

        for (int it = 0; it < NIT; ++it) {
            if (it + 1 < NIT) asm volatile("cp.async.wait_group 1;" ::: "memory");
            else              asm volatile("cp.async.wait_group 0;" ::: "memory");
            __syncthreads();

            if (it + 2 < NIT) issueB(it + 2, tid, sb, d0base, kbase);

            if (it + 1 < NIT) {
                char* Ap = smem + ((it + 1) & 1) * APSZ;
#pragma unroll
                for (int i = 0; i < 4; i++) {
                    const float4 v = rv[i];
                    if (db == 0) {
                        abs_acc   += fabsf(v.x) + fabsf(v.y) + fabsf(v.z) + fabsf(v.w);
                        plain_acc += (v.x + v.y) + (v.z + v.w);
                    }
                    uint2 u; u.x = pack_bf16x2(v.x, v.y); u.y = pack_bf16x2(v.z, v.w);
                    *reinterpret_cast<uint2*>(Ap + ap_off + (uint32_t)(i * 32 * P_STRIDE_H * 2)) = u;
                }
            }
            if (it + 2 < NIT) {
                const size_t ko = (size_t)(it + 2) * (KC / 4);
#pragma unroll
                for (int i = 0; i < 4; i++) rv[i] = ap[(size_t)i * 8 * NN + ko];
            }

            const uint32_t ab = a_base + (uint32_t)((it & 1) * APSZ);
            const uint32_t bb = b_base0 + (uint32_t)((it % 3) * BSZ);
#pragma unroll
            for (int kf = 0; kf < 2; kf++) {
                uint32_t bfr[2][4];
#pragma unroll
                for (int pr = 0; pr < 2; pr++)
                    ldm_x4(bfr[pr], bb + (uint32_t)(((pr * 16) * P_STRIDE_H + kf * 16) * 2));
                uint32_t afr[4][4];
#pragma unroll
                for (int mi = 0; mi < 4; mi++)
                    ldm_x4(afr[mi], ab + (uint32_t)(((mi * 16) * P_STRIDE_H + kf * 16) * 2));
#pragma unroll
                for (int mi = 0; mi < 4; mi++)
#pragma unroll
                    for (int ni = 0; ni < 4; ni++)
                        mma_16816(acc[mi][ni], afr[mi],
                                  bfr[ni >> 1][ni & 1], bfr[ni >> 1][(ni & 1) + 2]);
            }
        }

        // epilogue: sem contraction with coalesced ehatN reads
        float sem_acc = 0.f;
#pragma unroll
        for (int mi = 0; mi < 4; mi++)
#pragma unroll
            for (int ni = 0; ni < 4; ni++) {
                const int m0 = row0 + 64 * mq + 16 * mi + g;
                const int d0 = d0base + 32 * dq + 8 * ni + 2 * c;
                const __nv_bfloat162 e0 = *reinterpret_cast<const __nv_bfloat162*>(
                    &g_ehatN[(size_t)m0 * DD + d0]);
                const __nv_bfloat162 e1 = *reinterpret_cast<const __nv_bfloat162*>(
                    &g_ehatN[(size_t)(m0 + 8) * DD + d0]);
                sem_acc += acc[mi][ni][0] * __bfloat162float(e0.x)
                         + acc[mi][ni][1] * __bfloat162float(e0.y)
                         + acc[mi][ni][2] * __bfloat162float(e1.x)
                         + acc[mi][ni][3] * __bfloat162float(e1.y);
            }
#pragma unroll
        for (int o = 16; o; o >>= 1) {
            sem_acc   += __shfl_xor_sync(0xffffffffu, sem_acc, o);
            abs_acc   += __shfl_xor_sync(0xffffffffu, abs_acc, o);
            plain_acc += __shfl_xor_sync(0xffffffffu, plain_acc, o);
        }
        __syncthreads();
        if (lane == 0) { red[wid] = sem_acc; red[8 + wid] = abs_acc; red[16 + wid] = plain_acc; }
        __syncthreads();
        if (tid == 0) {
            float s2 = 0.f, a2 = 0.f, p2 = 0.f;
#pragma unroll
            for (int w = 0; w < 8; w++) { s2 += red[w]; a2 += red[8 + w]; p2 += red[16 + w]; }
            g_psem[t] = s2; g_pabs[t] = a2; g_pplain[t] = p2;
        }
        __syncthreads();
    }
}

// ---------------- kernel 3: combine (probe + CE gather + final) ----------------
__global__ void rdl_combine(const float* __restrict__ pred, const void* __restrict__ tgt,
                            float* __restrict__ out) {
    const int tid = threadIdx.x, lane = tid & 31, wid = tid >> 5;
    __shared__ float red[4][32];
    __shared__ int any;
    if (tid == 0) any = 0;
    __syncthreads();

    // probe target layout: int64 targets (<1000) => all odd words zero
    int local = 0;
    for (int i = tid; i < 2048; i += 1024) local |= ((const int*)tgt)[2 * i + 1];
    if (local) atomicOr(&any, 1);
    __syncthreads();
    const int is64 = (any == 0);

    float ce = 0.f, sem = 0.f, ab = 0.f, pl = 0.f;
    for (int r = tid; r < B_ROWS; r += 1024) {
        int t;
        if (is64) t = (int)((const long long*)tgt)[r];
        else      t = ((const int*)tgt)[r];
        t = min(max(t, 0), C_CLS - 1);
        ce += g_ce[r] - pred[(size_t)r * C_CLS + t];
    }
    for (int i = tid; i < TILES; i += 1024) { sem += g_psem[i]; ab += g_pabs[i]; pl += g_pplain[i]; }
#pragma unroll
    for (int o = 16; o; o >>= 1) {
        ce  += __shfl_xor_sync(0xffffffffu, ce, o);
        sem += __shfl_xor_sync(0xffffffffu, sem, o);
        ab  += __shfl_xor_sync(0xffffffffu, ab, o);
        pl  += __shfl_xor_sync(0xffffffffu, pl, o);
    }
    if (lane == 0) { red[0][wid] = ce; red[1][wid] = sem; red[2][wid] = ab; red[3][wid] = pl; }
    __syncthreads();
    if (tid == 0) {
        float tce = 0.f, tsem = 0.f, tab = 0.f, tpl = 0.f;
#pragma unroll
        for (int w = 0; w < 32; w++) {
            tce += red[0][w]; tsem += red[1][w]; tab += red[2][w]; tpl += red[3][w];
        }
        const float invB  = 1.0f / (float)B_ROWS;
        const float invN2 = 1.0f / ((float)NN * (float)NN);
        const float l_task   = tce * invB;
        const float l_sparse = tab * invN2;
        const float l_sem    = (tpl - tsem) * invN2;
        out[0] = 1.0f * l_task + 0.01f * l_sparse + 0.1f * l_sem;
    }
}

// ---------------- launch ----------------
extern "C" void kernel_launch(void* const* d_in, const int* in_sizes, int n_in,
                              void* d_out, int out_size) {
    const float* pred = nullptr; const void* tgt = nullptr;
    const float* adj  = nullptr; const float* emb = nullptr;
    for (int i = 0; i < n_in; i++) {
        switch (in_sizes[i]) {
            case B_ROWS * C_CLS:     pred = (const float*)d_in[i]; break;
            case B_ROWS:             tgt  = d_in[i];               break;
            case NN * NN:            adj  = (const float*)d_in[i]; break;
            case NN * DD:            emb  = (const float*)d_in[i]; break;
            default: break;
        }
    }
    float* out = (float*)d_out;
    (void)out_size;

    rdl_pre<<<256, THREADS>>>(emb);
    cudaFuncSetAttribute(rdl_main, cudaFuncAttributeMaxDynamicSharedMemorySize, SMEM_BYTES);
    rdl_main<<<PCTA, THREADS, SMEM_BYTES>>>(adj, pred);
    rdl_combine<<<1, 1024>>>(pred, tgt, out);
}

// round 16
// speedup vs baseline: 1.2043x; 1.0627x over previous
#include <cuda_runtime.h>
#include <cuda_bf16.h>
#include <cstdint>

// ---------------- problem constants ----------------
#define B_ROWS 4096
#define C_CLS  1000
#define NN     8192
#define DD     256

// main kernel tiling: tile = M128 x D128 x K2048; 64*2*4 = 512 tiles
#define MCTA    128
#define DCTA    128
#define KSPLIT  4
#define KC      32
#define KRANGE  (NN / KSPLIT)       // 2048
#define NIT     (KRANGE / KC)       // 64
#define TILES   512
#define PCTA    296                 // 2 CTAs x 148 SMs, persistent
#define THREADS 256

// smem: A' bf16 [128][40] x2, B bf16 [128][40] x3, red region
#define P_STRIDE_H 40
#define APSZ  (MCTA * P_STRIDE_H * 2)     // 10240
#define BSZ   (DCTA * P_STRIDE_H * 2)     // 10240
#define BOFF  (2 * APSZ)                  // 20480
#define REDOFF (2 * APSZ + 3 * BSZ)       // 51200
#define SMEM_BYTES (REDOFF + 128)         // 51328

// pre-kernel: 16 rows per block, padded tile stride (260 floats, 16B-aligned rows)
#define PR    16
#define TSTR  (DD + 4)

// ---------------- device scratch ----------------
__device__ __nv_bfloat16 g_ehatT[(size_t)DD * NN];  // Ê^T [256][8192]
__device__ __nv_bfloat16 g_ehatN[(size_t)NN * DD];  // Ê   [8192][256]
__device__ float g_ce[B_ROWS];                      // per-row logZ
__device__ float g_psem[TILES];
__device__ float g_pabs[TILES];
__device__ float g_pplain[TILES];
__device__ int   g_tile;

// ---------------- helpers ----------------
__device__ __forceinline__ uint32_t smem_u32(const void* p) {
    uint32_t a;
    asm("{ .reg .u64 t; cvta.to.shared.u64 t, %1; cvt.u32.u64 %0, t; }" : "=r"(a) : "l"(p));
    return a;
}
__device__ __forceinline__ void cp16(uint32_t s, const void* g) {
    asm volatile("cp.async.cg.shared.global [%0], [%1], 16;" :: "r"(s), "l"(g));
}
__device__ __forceinline__ void cp_commit() {
    asm volatile("cp.async.commit_group;" ::: "memory");
}
__device__ __forceinline__ void ldm_x4(uint32_t* r, uint32_t addr) {
    asm volatile("ldmatrix.sync.aligned.m8n8.x4.shared.b16 {%0,%1,%2,%3}, [%4];"
                 : "=r"(r[0]), "=r"(r[1]), "=r"(r[2]), "=r"(r[3]) : "r"(addr));
}
__device__ __forceinline__ void mma_16816(float* d, const uint32_t* a,
                                          uint32_t b0, uint32_t b1) {
    asm volatile(
        "mma.sync.aligned.m16n8k16.row.col.f32.bf16.bf16.f32 "
        "{%0,%1,%2,%3}, {%4,%5,%6,%7}, {%8,%9}, {%0,%1,%2,%3};"
        : "+f"(d[0]), "+f"(d[1]), "+f"(d[2]), "+f"(d[3])
        : "r"(a[0]), "r"(a[1]), "r"(a[2]), "r"(a[3]), "r"(b0), "r"(b1));
}
__device__ __forceinline__ uint32_t pack_bf16x2(float lo, float hi) {
    __nv_bfloat162 h = __floats2bfloat162_rn(lo, hi);
    return *reinterpret_cast<uint32_t*>(&h);
}

// ---------------- kernel 1: norm-only pre (+ queue reset), 512 blocks x 16 rows ----------------
__global__ void rdl_pre(const float* __restrict__ emb) {
    const int tid = threadIdx.x, lane = tid & 31, wid = tid >> 5;
    if (blockIdx.x == 0 && tid == 0) g_tile = 0;

    __shared__ float tile[PR * TSTR];
    __shared__ float rnorm[PR];
    const int r0 = blockIdx.x * PR;

    // load 16x256 floats via float4 into padded tile
#pragma unroll
    for (int i = tid; i < PR * DD / 4; i += 256) {
        const int r = i >> 6, c4 = i & 63;   // DD/4 = 64
        *reinterpret_cast<float4*>(&tile[r * TSTR + c4 * 4]) =
            *reinterpret_cast<const float4*>(emb + (size_t)(r0 + r) * DD + c4 * 4);
    }
    __syncthreads();

    // 8 warps x 2 rows: row norms
#pragma unroll
    for (int q = 0; q < 2; q++) {
        const int rr = wid * 2 + q;
        float s = 0.f;
#pragma unroll
        for (int kk = lane; kk < DD; kk += 32) { float v = tile[rr * TSTR + kk]; s += v * v; }
#pragma unroll
        for (int o = 16; o; o >>= 1) s += __shfl_xor_sync(0xffffffffu, s, o);
        if (lane == 0) rnorm[rr] = rsqrtf(s);
    }
    __syncthreads();

    // transposed copy: warp wid handles d = d8*8+wid, lanes 0..15 = rows
    if (lane < PR) {
        const float rn = rnorm[lane];
#pragma unroll
        for (int d8 = 0; d8 < 32; d8++) {
            const int d = d8 * 8 + wid;
            g_ehatT[(size_t)d * NN + r0 + lane] = __float2bfloat16(tile[lane * TSTR + d] * rn);
        }
    }
    // plain copy (coalesced, 4 bf16 per store)
#pragma unroll
    for (int i = tid; i < PR * DD / 4; i += 256) {
        const int r = i >> 6, c4 = i & 63;
        const float4 v = *reinterpret_cast<const float4*>(&tile[r * TSTR + c4 * 4]);
        const float rn = rnorm[r];
        uint2 u;
        u.x = pack_bf16x2(v.x * rn, v.y * rn);
        u.y = pack_bf16x2(v.z * rn, v.w * rn);
        *reinterpret_cast<uint2*>(&g_ehatN[(size_t)(r0 + r) * DD + c4 * 4]) = u;
    }
}

// ---------------- kernel 2: persistent main (CE pre-phase + GEMM tiles) ----------------
__device__ __forceinline__ void issueB(int it, int tid, uint32_t sb, int d0, int kbase) {
    const uint32_t sbb = sb + BOFF + (uint32_t)((it % 3) * BSZ);
    const int kb = kbase + it * KC;
#pragma unroll
    for (int i = 0; i < 2; i++) {
        const int idx = tid + (i << 8);
        const int r = idx >> 2, c = idx & 3;
        cp16(sbb + r * (P_STRIDE_H * 2) + c * 16,
             reinterpret_cast<const char*>(g_ehatT) +
                 ((size_t)(d0 + r) * NN + (unsigned)(kb + c * 8)) * 2);
    }
    cp_commit();
}

__global__ __launch_bounds__(THREADS, 2) void rdl_main(const float* __restrict__ adj,
                                                       const float* __restrict__ pred) {
    extern __shared__ char smem[];
    const int tid = threadIdx.x, wid = tid >> 5, lane = tid & 31;
    const uint32_t sb = smem_u32(smem);

    // ---- CE pre-phase: per-row logZ, warp-per-row ----
    for (int row = blockIdx.x * 8 + wid; row < B_ROWS; row += PCTA * 8) {
        const float4* p4 = reinterpret_cast<const float4*>(pred + (size_t)row * C_CLS);
        float m = -3.4e38f;
        for (int i = lane; i < C_CLS / 4; i += 32) {
            const float4 v = p4[i];
            m = fmaxf(m, fmaxf(fmaxf(v.x, v.y), fmaxf(v.z, v.w)));
        }
#pragma unroll
        for (int o = 16; o; o >>= 1) m = fmaxf(m, __shfl_xor_sync(0xffffffffu, m, o));
        float s = 0.f;
        for (int i = lane; i < C_CLS / 4; i += 32) {
            const float4 v = p4[i];
            s += expf(v.x - m) + expf(v.y - m) + expf(v.z - m) + expf(v.w - m);
        }
#pragma unroll
        for (int o = 16; o; o >>= 1) s += __shfl_xor_sync(0xffffffffu, s, o);
        if (lane == 0) g_ce[row] = m + logf(s);   // logZ
    }

    // ---- GEMM tile phase ----
    const int mq = wid & 1;                  // M half (64 rows)
    const int dq = wid >> 1;                 // D quarter (32 cols)
    const int g = lane >> 2, c = lane & 3;

    const int lrow = lane & 15, lcol8 = (lane >> 4) << 3;
    const uint32_t a_base = sb + (uint32_t)(((64 * mq + lrow) * P_STRIDE_H + lcol8) * 2);
    const uint32_t b_base0 = sb + BOFF + (uint32_t)(((32 * dq + lrow) * P_STRIDE_H + lcol8) * 2);

    const int cv_r = tid >> 3, cv_c = tid & 7;
    const uint32_t ap_off = (uint32_t)((cv_r * P_STRIDE_H + cv_c * 4) * 2);

    int* tile_sh = reinterpret_cast<int*>(smem + REDOFF + 96);
    float* red = reinterpret_cast<float*>(smem + REDOFF);

    for (;;) {
        if (tid == 0) *tile_sh = atomicAdd(&g_tile, 1);
        __syncthreads();
        const int t = *tile_sh;
        __syncthreads();
        if (t >= TILES) break;

        const int row0   = (t & 63) * MCTA;
        const int db     = (t >> 6) & 1;
        const int d0base = db * DCTA;
        const int kbase  = (t >> 7) * KRANGE;

        const float4* ap = reinterpret_cast<const float4*>(
            adj + (size_t)(row0 + cv_r) * NN + (unsigned)kbase) + cv_c;

        float acc[4][4][4];
#pragma unroll
        for (int mi = 0; mi < 4; mi++)
#pragma unroll
            for (int ni = 0; ni < 4; ni++)
#pragma unroll
                for (int q = 0; q < 4; q++) acc[mi][ni][q] = 0.f;

        float abs_acc = 0.f, plain_acc = 0.f;
        float4 rv[4];

        // prologue
        issueB(0, tid, sb, d0base, kbase);
        issueB(1, tid, sb, d0base, kbase);
#pragma unroll
        for (int i = 0; i < 4; i++) rv[i] = ap[(size_t)i * 8 * NN];
#pragma unroll
        for (int i = 0; i < 4; i++) {
            const float4 v = rv[i];
            if (db == 0) {
                abs_acc   += fabsf(v.x) + fabsf(v.y) + fabsf(v.z) + fabsf(v.w);
                plain_acc += (v.x + v.y) + (v.z + v.w);
            }
            uint2 u; u.x = pack_bf16x2(v.x, v.y); u.y = pack_bf16x2(v.z, v.w);
            *reinterpret_cast<uint2*>(smem + ap_off + (uint32_t)(i * 32 * P_STRIDE_H * 2)) = u;
        }
#pragma unroll
        for (int i = 0; i < 4; i++) rv[i] = ap[(size_t)i * 8 * NN + 8];

        for (int it = 0; it < NIT; ++it) {
            if (it + 1 < NIT) asm volatile("cp.async.wait_group 1;" ::: "memory");
            else              asm volatile("cp.async.wait_group 0;" ::: "memory");
            __syncthreads();

            if (it + 2 < NIT) issueB(it + 2, tid, sb, d0base, kbase);

            if (it + 1 < NIT) {
                char* Ap = smem + ((it + 1) & 1) * APSZ;
#pragma unroll
                for (int i = 0; i < 4; i++) {
                    const float4 v = rv[i];
                    if (db == 0) {
                        abs_acc   += fabsf(v.x) + fabsf(v.y) + fabsf(v.z) + fabsf(v.w);
                        plain_acc += (v.x + v.y) + (v.z + v.w);
                    }
                    uint2 u; u.x = pack_bf16x2(v.x, v.y); u.y = pack_bf16x2(v.z, v.w);
                    *reinterpret_cast<uint2*>(Ap + ap_off + (uint32_t)(i * 32 * P_STRIDE_H * 2)) = u;
                }
            }
            if (it + 2 < NIT) {
                const size_t ko = (size_t)(it + 2) * (KC / 4);
#pragma unroll
                for (int i = 0; i < 4; i++) rv[i] = ap[(size_t)i * 8 * NN + ko];
            }

            const uint32_t ab = a_base + (uint32_t)((it & 1) * APSZ);
            const uint32_t bb = b_base0 + (uint32_t)((it % 3) * BSZ);
#pragma unroll
            for (int kf = 0; kf < 2; kf++) {
                uint32_t bfr[2][4];
#pragma unroll
                for (int pr = 0; pr < 2; pr++)
                    ldm_x4(bfr[pr], bb + (uint32_t)(((pr * 16) * P_STRIDE_H + kf * 16) * 2));
                uint32_t afr[4][4];
#pragma unroll
                for (int mi = 0; mi < 4; mi++)
                    ldm_x4(afr[mi], ab + (uint32_t)(((mi * 16) * P_STRIDE_H + kf * 16) * 2));
#pragma unroll
                for (int mi = 0; mi < 4; mi++)
#pragma unroll
                    for (int ni = 0; ni < 4; ni++)
                        mma_16816(acc[mi][ni], afr[mi],
                                  bfr[ni >> 1][ni & 1], bfr[ni >> 1][(ni & 1) + 2]);
            }
        }

        // epilogue: sem contraction with coalesced ehatN reads
        float sem_acc = 0.f;
#pragma unroll
        for (int mi = 0; mi < 4; mi++)
#pragma unroll
            for (int ni = 0; ni < 4; ni++) {
                const int m0 = row0 + 64 * mq + 16 * mi + g;
                const int d0 = d0base + 32 * dq + 8 * ni + 2 * c;
                const __nv_bfloat162 e0 = *reinterpret_cast<const __nv_bfloat162*>(
                    &g_ehatN[(size_t)m0 * DD + d0]);
                const __nv_bfloat162 e1 = *reinterpret_cast<const __nv_bfloat162*>(
                    &g_ehatN[(size_t)(m0 + 8) * DD + d0]);
                sem_acc += acc[mi][ni][0] * __bfloat162float(e0.x)
                         + acc[mi][ni][1] * __bfloat162float(e0.y)
                         + acc[mi][ni][2] * __bfloat162float(e1.x)
                         + acc[mi][ni][3] * __bfloat162float(e1.y);
            }
#pragma unroll
        for (int o = 16; o; o >>= 1) {
            sem_acc   += __shfl_xor_sync(0xffffffffu, sem_acc, o);
            abs_acc   += __shfl_xor_sync(0xffffffffu, abs_acc, o);
            plain_acc += __shfl_xor_sync(0xffffffffu, plain_acc, o);
        }
        __syncthreads();
        if (lane == 0) { red[wid] = sem_acc; red[8 + wid] = abs_acc; red[16 + wid] = plain_acc; }
        __syncthreads();
        if (tid == 0) {
            float s2 = 0.f, a2 = 0.f, p2 = 0.f;
#pragma unroll
            for (int w = 0; w < 8; w++) { s2 += red[w]; a2 += red[8 + w]; p2 += red[16 + w]; }
            g_psem[t] = s2; g_pabs[t] = a2; g_pplain[t] = p2;
        }
        __syncthreads();
    }
}

// ---------------- kernel 3: combine (probe + CE gather + final) ----------------
__global__ void rdl_combine(const float* __restrict__ pred, const void* __restrict__ tgt,
                            float* __restrict__ out) {
    const int tid = threadIdx.x, lane = tid & 31, wid = tid >> 5;
    __shared__ float red[4][32];
    __shared__ int any;
    if (tid == 0) any = 0;
    __syncthreads();

    // probe target layout: int64 targets (<1000) => all odd words zero
    int local = 0;
    for (int i = tid; i < 2048; i += 1024) local |= ((const int*)tgt)[2 * i + 1];
    if (local) atomicOr(&any, 1);
    __syncthreads();
    const int is64 = (any == 0);

    float ce = 0.f, sem = 0.f, ab = 0.f, pl = 0.f;
    for (int r = tid; r < B_ROWS; r += 1024) {
        int t;
        if (is64) t = (int)((const long long*)tgt)[r];
        else      t = ((const int*)tgt)[r];
        t = min(max(t, 0), C_CLS - 1);
        ce += g_ce[r] - pred[(size_t)r * C_CLS + t];
    }
    for (int i = tid; i < TILES; i += 1024) { sem += g_psem[i]; ab += g_pabs[i]; pl += g_pplain[i]; }
#pragma unroll
    for (int o = 16; o; o >>= 1) {
        ce  += __shfl_xor_sync(0xffffffffu, ce, o);
        sem += __shfl_xor_sync(0xffffffffu, sem, o);
        ab  += __shfl_xor_sync(0xffffffffu, ab, o);
        pl  += __shfl_xor_sync(0xffffffffu, pl, o);
    }
    if (lane == 0) { red[0][wid] = ce; red[1][wid] = sem; red[2][wid] = ab; red[3][wid] = pl; }
    __syncthreads();
    if (tid == 0) {
        float tce = 0.f, tsem = 0.f, tab = 0.f, tpl = 0.f;
#pragma unroll
        for (int w = 0; w < 32; w++) {
            tce += red[0][w]; tsem += red[1][w]; tab += red[2][w]; tpl += red[3][w];
        }
        const float invB  = 1.0f / (float)B_ROWS;
        const float invN2 = 1.0f / ((float)NN * (float)NN);
        const float l_task   = tce * invB;
        const float l_sparse = tab * invN2;
        const float l_sem    = (tpl - tsem) * invN2;
        out[0] = 1.0f * l_task + 0.01f * l_sparse + 0.1f * l_sem;
    }
}

// ---------------- launch ----------------
extern "C" void kernel_launch(void* const* d_in, const int* in_sizes, int n_in,
                              void* d_out, int out_size) {
    const float* pred = nullptr; const void* tgt = nullptr;
    const float* adj  = nullptr; const float* emb = nullptr;
    for (int i = 0; i < n_in; i++) {
        switch (in_sizes[i]) {
            case B_ROWS * C_CLS:     pred = (const float*)d_in[i]; break;
            case B_ROWS:             tgt  = d_in[i];               break;
            case NN * NN:            adj  = (const float*)d_in[i]; break;
            case NN * DD:            emb  = (const float*)d_in[i]; break;
            default: break;
        }
    }
    float* out = (float*)d_out;
    (void)out_size;

    rdl_pre<<<NN / PR, THREADS>>>(emb);
    cudaFuncSetAttribute(rdl_main, cudaFuncAttributeMaxDynamicSharedMemorySize, SMEM_BYTES);
    rdl_main<<<PCTA, THREADS, SMEM_BYTES>>>(adj, pred);
    rdl_combine<<<1, 1024>>>(pred, tgt, out);
}